// round 2
// baseline (speedup 1.0000x reference)
#include <cuda_runtime.h>

// Problem constants
#define B_    8
#define CIN_  512
#define COUT_ 3
#define WDIM_ 512
#define HW_   65536           // 256*256
#define HW4_  (HW_/4)         // 16384 float4s per channel plane
#define CLAMP_ 256.0f

// Scratch: per-(batch, cin) premultiplied modulation, padded to float4:
//   g_m[((b*CIN)+c)*4 + o] = weight[o][c] * styles[b][c]   (o in 0..2, slot 3 unused)
__device__ float g_m[B_ * CIN_ * 4];

__forceinline__ __device__ float clamp_rgb(float v) {
    return fminf(fmaxf(v, -CLAMP_), CLAMP_);
}

// ---------------------------------------------------------------------------
// Kernel 1: styles + premultiply (tiny: 8 blocks x 512 threads, ~2 MFLOP)
// styles[b][c] = (dot(w[b,:], affine_w[c,:]) / sqrt(WDIM) + affine_b[c]) / sqrt(CIN)
// ---------------------------------------------------------------------------
__global__ void __launch_bounds__(WDIM_) styles_kernel(
    const float* __restrict__ w,        // [B, WDIM]
    const float* __restrict__ weight,   // [COUT, CIN] (1x1 conv squeezed)
    const float* __restrict__ affine_w, // [CIN, WDIM]
    const float* __restrict__ affine_b) // [CIN]
{
    __shared__ float wsh[WDIM_];
    const int b = blockIdx.x;
    const int c = threadIdx.x;

    wsh[c] = w[b * WDIM_ + c];
    __syncthreads();

    const float4* aw = reinterpret_cast<const float4*>(affine_w + (size_t)c * WDIM_);
    const float4* ws = reinterpret_cast<const float4*>(wsh);

    float acc = 0.0f;
#pragma unroll 8
    for (int d = 0; d < WDIM_ / 4; d++) {
        float4 a = aw[d];
        float4 v = ws[d];
        acc += a.x * v.x + a.y * v.y + a.z * v.z + a.w * v.w;
    }

    const float ga = 1.0f / sqrtf((float)WDIM_);   // constant-folded
    const float gc = 1.0f / sqrtf((float)CIN_);
    const float style = (acc * ga + affine_b[c]) * gc;

    float4 mv;
    mv.x = weight[0 * CIN_ + c] * style;
    mv.y = weight[1 * CIN_ + c] * style;
    mv.z = weight[2 * CIN_ + c] * style;
    mv.w = 0.0f;
    reinterpret_cast<float4*>(g_m)[b * CIN_ + c] = mv;
}

// ---------------------------------------------------------------------------
// Kernel 2: the streaming reduction. HBM-bound: reads x (1.074 GB) once.
// Each thread owns one float4 of pixels; loops over C=512 with unroll 8
// (8 outstanding LDG.128 -> MLP hides DRAM latency). m slice in smem,
// broadcast LDS.128 per c-iter. 12 FFMA per 16 bytes loaded.
// grid = B * (HW/1024) = 8 * 64 = 512 blocks, 256 threads.
// ---------------------------------------------------------------------------
__global__ void __launch_bounds__(256) torgb_kernel(
    const float* __restrict__ x,     // [B, CIN, H, W]
    const float* __restrict__ bias,  // [COUT]
    float* __restrict__ out)         // [B, COUT, H, W]
{
    __shared__ float4 sm[CIN_];

    const int b    = blockIdx.x >> 6;        // 64 tiles per batch
    const int tile = blockIdx.x & 63;
    const int tid  = threadIdx.x;

    // Stage this batch's modulation vector into smem (8 KB)
    const float4* gm = reinterpret_cast<const float4*>(g_m) + (size_t)b * CIN_;
#pragma unroll
    for (int i = tid; i < CIN_; i += 256) sm[i] = gm[i];
    __syncthreads();

    const int p4 = tile * 256 + tid;          // float4 index within plane [0, 16384)
    const float4* xp = reinterpret_cast<const float4*>(x)
                     + (size_t)b * CIN_ * HW4_ + p4;

    float4 a0 = {0.f, 0.f, 0.f, 0.f};
    float4 a1 = {0.f, 0.f, 0.f, 0.f};
    float4 a2 = {0.f, 0.f, 0.f, 0.f};

#pragma unroll 8
    for (int c = 0; c < CIN_; c++) {
        float4 xv = xp[(size_t)c * HW4_];
        float4 mv = sm[c];
        a0.x += xv.x * mv.x; a0.y += xv.y * mv.x;
        a0.z += xv.z * mv.x; a0.w += xv.w * mv.x;
        a1.x += xv.x * mv.y; a1.y += xv.y * mv.y;
        a1.z += xv.z * mv.y; a1.w += xv.w * mv.y;
        a2.x += xv.x * mv.z; a2.y += xv.y * mv.z;
        a2.z += xv.z * mv.z; a2.w += xv.w * mv.z;
    }

    const float b0 = bias[0], b1 = bias[1], b2 = bias[2];
    a0.x = clamp_rgb(a0.x + b0); a0.y = clamp_rgb(a0.y + b0);
    a0.z = clamp_rgb(a0.z + b0); a0.w = clamp_rgb(a0.w + b0);
    a1.x = clamp_rgb(a1.x + b1); a1.y = clamp_rgb(a1.y + b1);
    a1.z = clamp_rgb(a1.z + b1); a1.w = clamp_rgb(a1.w + b1);
    a2.x = clamp_rgb(a2.x + b2); a2.y = clamp_rgb(a2.y + b2);
    a2.z = clamp_rgb(a2.z + b2); a2.w = clamp_rgb(a2.w + b2);

    float4* op = reinterpret_cast<float4*>(out) + (size_t)b * COUT_ * HW4_ + p4;
    op[0 * HW4_] = a0;
    op[1 * HW4_] = a1;
    op[2 * HW4_] = a2;
}

// ---------------------------------------------------------------------------
// Launch. Inputs (metadata order): x, w, weight, bias, affine_w, affine_b
// ---------------------------------------------------------------------------
extern "C" void kernel_launch(void* const* d_in, const int* in_sizes, int n_in,
                              void* d_out, int out_size)
{
    const float* x        = (const float*)d_in[0];
    const float* w        = (const float*)d_in[1];
    const float* weight   = (const float*)d_in[2];
    const float* bias     = (const float*)d_in[3];
    const float* affine_w = (const float*)d_in[4];
    const float* affine_b = (const float*)d_in[5];
    float* out = (float*)d_out;

    styles_kernel<<<B_, WDIM_>>>(w, weight, affine_w, affine_b);
    torgb_kernel<<<B_ * (HW_ / 1024), 256>>>(x, bias, out);
}

// round 3
// speedup vs baseline: 1.0820x; 1.0820x over previous
#include <cuda_runtime.h>

// Problem constants
#define B_    8
#define CIN_  512
#define COUT_ 3
#define WDIM_ 512
#define HW_   65536           // 256*256
#define HW4_  (HW_/4)         // 16384 float4s per channel plane
#define CLAMP_ 256.0f

// Scratch: per-(batch, cin) premultiplied modulation, padded to float4:
//   g_m[((b*CIN)+c)*4 + o] = weight[o][c] * styles[b][c]   (o in 0..2, slot 3 unused)
__device__ float g_m[B_ * CIN_ * 4];

__forceinline__ __device__ float clamp_rgb(float v) {
    return fminf(fmaxf(v, -CLAMP_), CLAMP_);
}

// ---------------------------------------------------------------------------
// Kernel 1: styles + premultiply. One WARP per (b,c) pair.
// 4096 pairs -> grid 512 x 256 (8 warps/block). Each lane reads 16 floats of
// affine_w row c (4x LDG.128) and 16 of w row b, partial dot, shuffle-reduce.
// Fully occupies the chip; predicted ~4us (was ~39us at grid=8).
// ---------------------------------------------------------------------------
__global__ void __launch_bounds__(256) styles_kernel(
    const float* __restrict__ w,        // [B, WDIM]
    const float* __restrict__ weight,   // [COUT, CIN] (1x1 conv squeezed)
    const float* __restrict__ affine_w, // [CIN, WDIM]
    const float* __restrict__ affine_b) // [CIN]
{
    const int warp_id = (blockIdx.x * blockDim.x + threadIdx.x) >> 5;  // 0..4095
    const int lane    = threadIdx.x & 31;
    const int b = warp_id >> 9;        // /CIN_
    const int c = warp_id & (CIN_ - 1);

    // Each lane: 4 float4 = 16 elements, strided across the warp.
    const float4* aw = reinterpret_cast<const float4*>(affine_w + (size_t)c * WDIM_);
    const float4* wv = reinterpret_cast<const float4*>(w + (size_t)b * WDIM_);

    float acc = 0.0f;
#pragma unroll
    for (int i = 0; i < 4; i++) {
        const int d = i * 32 + lane;   // float4 index in [0,128)
        float4 a = aw[d];
        float4 v = wv[d];
        acc += a.x * v.x + a.y * v.y + a.z * v.z + a.w * v.w;
    }
    // warp reduction
#pragma unroll
    for (int off = 16; off > 0; off >>= 1)
        acc += __shfl_xor_sync(0xFFFFFFFF, acc, off);

    if (lane == 0) {
        const float ga = 1.0f / sqrtf((float)WDIM_);
        const float gc = 1.0f / sqrtf((float)CIN_);
        const float style = (acc * ga + affine_b[c]) * gc;
        float4 mv;
        mv.x = weight[0 * CIN_ + c] * style;
        mv.y = weight[1 * CIN_ + c] * style;
        mv.z = weight[2 * CIN_ + c] * style;
        mv.w = 0.0f;
        reinterpret_cast<float4*>(g_m)[b * CIN_ + c] = mv;
    }
}

// ---------------------------------------------------------------------------
// Kernel 2: the streaming reduction. HBM-bound: reads x (1.074 GB) once.
// Each thread owns one float4 of pixels; loops over C=512 with unroll 8
// (8 outstanding LDG.128 -> MLP hides DRAM latency). m slice in smem,
// broadcast LDS.128 per c-iter. 12 FFMA per 16 bytes loaded.
// grid = B * (HW4/128) = 1024 blocks, 128 threads (better SM balance than
// 512x256: 6.9 blocks/SM vs 3.46 -> smaller tail quantum).
// ---------------------------------------------------------------------------
__global__ void __launch_bounds__(128) torgb_kernel(
    const float* __restrict__ x,     // [B, CIN, H, W]
    const float* __restrict__ bias,  // [COUT]
    float* __restrict__ out)         // [B, COUT, H, W]
{
    __shared__ float4 sm[CIN_];

    const int b    = blockIdx.x >> 7;         // 128 tiles per batch
    const int tile = blockIdx.x & 127;
    const int tid  = threadIdx.x;

    // Stage this batch's modulation vector into smem (8 KB)
    const float4* gm = reinterpret_cast<const float4*>(g_m) + (size_t)b * CIN_;
#pragma unroll
    for (int i = tid; i < CIN_; i += 128) sm[i] = gm[i];
    __syncthreads();

    const int p4 = tile * 128 + tid;          // float4 index within plane [0, 16384)
    const float4* xp = reinterpret_cast<const float4*>(x)
                     + (size_t)b * CIN_ * HW4_ + p4;

    float4 a0 = {0.f, 0.f, 0.f, 0.f};
    float4 a1 = {0.f, 0.f, 0.f, 0.f};
    float4 a2 = {0.f, 0.f, 0.f, 0.f};

#pragma unroll 8
    for (int c = 0; c < CIN_; c++) {
        float4 xv = xp[(size_t)c * HW4_];
        float4 mv = sm[c];
        a0.x += xv.x * mv.x; a0.y += xv.y * mv.x;
        a0.z += xv.z * mv.x; a0.w += xv.w * mv.x;
        a1.x += xv.x * mv.y; a1.y += xv.y * mv.y;
        a1.z += xv.z * mv.y; a1.w += xv.w * mv.y;
        a2.x += xv.x * mv.z; a2.y += xv.y * mv.z;
        a2.z += xv.z * mv.z; a2.w += xv.w * mv.z;
    }

    const float b0 = bias[0], b1 = bias[1], b2 = bias[2];
    a0.x = clamp_rgb(a0.x + b0); a0.y = clamp_rgb(a0.y + b0);
    a0.z = clamp_rgb(a0.z + b0); a0.w = clamp_rgb(a0.w + b0);
    a1.x = clamp_rgb(a1.x + b1); a1.y = clamp_rgb(a1.y + b1);
    a1.z = clamp_rgb(a1.z + b1); a1.w = clamp_rgb(a1.w + b1);
    a2.x = clamp_rgb(a2.x + b2); a2.y = clamp_rgb(a2.y + b2);
    a2.z = clamp_rgb(a2.z + b2); a2.w = clamp_rgb(a2.w + b2);

    float4* op = reinterpret_cast<float4*>(out) + (size_t)b * COUT_ * HW4_ + p4;
    op[0 * HW4_] = a0;
    op[1 * HW4_] = a1;
    op[2 * HW4_] = a2;
}

// ---------------------------------------------------------------------------
// Launch. Inputs (metadata order): x, w, weight, bias, affine_w, affine_b
// ---------------------------------------------------------------------------
extern "C" void kernel_launch(void* const* d_in, const int* in_sizes, int n_in,
                              void* d_out, int out_size)
{
    const float* x        = (const float*)d_in[0];
    const float* w        = (const float*)d_in[1];
    const float* weight   = (const float*)d_in[2];
    const float* bias     = (const float*)d_in[3];
    const float* affine_w = (const float*)d_in[4];
    const float* affine_b = (const float*)d_in[5];
    float* out = (float*)d_out;

    styles_kernel<<<(B_ * CIN_) / 8, 256>>>(w, weight, affine_w, affine_b);
    torgb_kernel<<<B_ * (HW4_ / 128), 128>>>(x, bias, out);
}

// round 4
// speedup vs baseline: 1.2797x; 1.1827x over previous
#include <cuda_runtime.h>

// Problem constants
#define B_    8
#define CIN_  512
#define COUT_ 3
#define WDIM_ 512
#define HW_   65536           // 256*256
#define HW4_  (HW_/4)         // 16384 float4s per channel plane
#define CLAMP_ 256.0f

// Scratch: per-(batch, cin) premultiplied modulation, padded to float4:
//   g_m[((b*CIN)+c)*4 + o] = weight[o][c] * styles[b][c]   (o in 0..2, slot 3 unused)
__device__ float g_m[B_ * CIN_ * 4];

__forceinline__ __device__ float clamp_rgb(float v) {
    return fminf(fmaxf(v, -CLAMP_), CLAMP_);
}

// ---------------------------------------------------------------------------
// Kernel 1: styles + premultiply. One WARP per (b,c) pair.
// 4096 pairs -> grid 512 x 256 (8 warps/block). ~4us measured.
// ---------------------------------------------------------------------------
__global__ void __launch_bounds__(256) styles_kernel(
    const float* __restrict__ w,        // [B, WDIM]
    const float* __restrict__ weight,   // [COUT, CIN] (1x1 conv squeezed)
    const float* __restrict__ affine_w, // [CIN, WDIM]
    const float* __restrict__ affine_b) // [CIN]
{
    const int warp_id = (blockIdx.x * blockDim.x + threadIdx.x) >> 5;  // 0..4095
    const int lane    = threadIdx.x & 31;
    const int b = warp_id >> 9;        // /CIN_
    const int c = warp_id & (CIN_ - 1);

    const float4* aw = reinterpret_cast<const float4*>(affine_w + (size_t)c * WDIM_);
    const float4* wv = reinterpret_cast<const float4*>(w + (size_t)b * WDIM_);

    float acc = 0.0f;
#pragma unroll
    for (int i = 0; i < 4; i++) {
        const int d = i * 32 + lane;   // float4 index in [0,128)
        float4 a = aw[d];
        float4 v = wv[d];
        acc += a.x * v.x + a.y * v.y + a.z * v.z + a.w * v.w;
    }
#pragma unroll
    for (int off = 16; off > 0; off >>= 1)
        acc += __shfl_xor_sync(0xFFFFFFFF, acc, off);

    if (lane == 0) {
        const float ga = 1.0f / sqrtf((float)WDIM_);
        const float gc = 1.0f / sqrtf((float)CIN_);
        const float style = (acc * ga + affine_b[c]) * gc;
        float4 mv;
        mv.x = weight[0 * CIN_ + c] * style;
        mv.y = weight[1 * CIN_ + c] * style;
        mv.z = weight[2 * CIN_ + c] * style;
        mv.w = 0.0f;
        reinterpret_cast<float4*>(g_m)[b * CIN_ + c] = mv;
    }
}

// ---------------------------------------------------------------------------
// Kernel 2: streaming reduction, reads x (1.074 GB) exactly once.
// REVERTED to the measured-best shape: grid 512 x 256 threads, one float4
// per thread (4KB contiguous per block per channel-iter; 171.8us @ 79% DRAM
// in R2 vs 190.6us @ 71% with 128-thread blocks in R3).
// NEW: __ldcs/__stcs evict-first hints - x and out are strictly streamed.
// ---------------------------------------------------------------------------
__global__ void __launch_bounds__(256) torgb_kernel(
    const float* __restrict__ x,     // [B, CIN, H, W]
    const float* __restrict__ bias,  // [COUT]
    float* __restrict__ out)         // [B, COUT, H, W]
{
    __shared__ float4 sm[CIN_];

    const int b    = blockIdx.x >> 6;        // 64 tiles per batch
    const int tile = blockIdx.x & 63;
    const int tid  = threadIdx.x;

    // Stage this batch's modulation vector into smem (8 KB)
    const float4* gm = reinterpret_cast<const float4*>(g_m) + (size_t)b * CIN_;
#pragma unroll
    for (int i = tid; i < CIN_; i += 256) sm[i] = gm[i];
    __syncthreads();

    const int p4 = tile * 256 + tid;          // float4 index within plane [0, 16384)
    const float4* xp = reinterpret_cast<const float4*>(x)
                     + (size_t)b * CIN_ * HW4_ + p4;

    float4 a0 = {0.f, 0.f, 0.f, 0.f};
    float4 a1 = {0.f, 0.f, 0.f, 0.f};
    float4 a2 = {0.f, 0.f, 0.f, 0.f};

#pragma unroll 8
    for (int c = 0; c < CIN_; c++) {
        float4 xv = __ldcs(xp + (size_t)c * HW4_);   // streaming: evict-first
        float4 mv = sm[c];
        a0.x += xv.x * mv.x; a0.y += xv.y * mv.x;
        a0.z += xv.z * mv.x; a0.w += xv.w * mv.x;
        a1.x += xv.x * mv.y; a1.y += xv.y * mv.y;
        a1.z += xv.z * mv.y; a1.w += xv.w * mv.y;
        a2.x += xv.x * mv.z; a2.y += xv.y * mv.z;
        a2.z += xv.z * mv.z; a2.w += xv.w * mv.z;
    }

    const float b0 = bias[0], b1 = bias[1], b2 = bias[2];
    a0.x = clamp_rgb(a0.x + b0); a0.y = clamp_rgb(a0.y + b0);
    a0.z = clamp_rgb(a0.z + b0); a0.w = clamp_rgb(a0.w + b0);
    a1.x = clamp_rgb(a1.x + b1); a1.y = clamp_rgb(a1.y + b1);
    a1.z = clamp_rgb(a1.z + b1); a1.w = clamp_rgb(a1.w + b1);
    a2.x = clamp_rgb(a2.x + b2); a2.y = clamp_rgb(a2.y + b2);
    a2.z = clamp_rgb(a2.z + b2); a2.w = clamp_rgb(a2.w + b2);

    float4* op = reinterpret_cast<float4*>(out) + (size_t)b * COUT_ * HW4_ + p4;
    __stcs(op + 0 * HW4_, a0);
    __stcs(op + 1 * HW4_, a1);
    __stcs(op + 2 * HW4_, a2);
}

// ---------------------------------------------------------------------------
// Launch. Inputs (metadata order): x, w, weight, bias, affine_w, affine_b
// ---------------------------------------------------------------------------
extern "C" void kernel_launch(void* const* d_in, const int* in_sizes, int n_in,
                              void* d_out, int out_size)
{
    const float* x        = (const float*)d_in[0];
    const float* w        = (const float*)d_in[1];
    const float* weight   = (const float*)d_in[2];
    const float* bias     = (const float*)d_in[3];
    const float* affine_w = (const float*)d_in[4];
    const float* affine_b = (const float*)d_in[5];
    float* out = (float*)d_out;

    styles_kernel<<<(B_ * CIN_) / 8, 256>>>(w, weight, affine_w, affine_b);
    torgb_kernel<<<B_ * (HW_ / 1024), 256>>>(x, bias, out);
}